// round 1
// baseline (speedup 1.0000x reference)
#include <cuda_runtime.h>
#include <math.h>

#define F_ 4
#define V_ 4
#define E_ 64
#define NIN_ 1024
#define N_ 1024
#define M_ 1026
#define FV_ (F_*V_)

// ---------------- scratch (static device globals; no allocation) ----------------
__device__ float g_theta[M_*N_];           // forward theta (clipped + zeroed)
__device__ float g_gt[M_*N_];              // g_tilde
__device__ unsigned int g_gmin_bits[N_];   // column min of |clip(theta)| as uint bits
__device__ float g_gs[N_];                 // sum_m gt
__device__ int   g_actsel[N_];             // hard gumbel pick for activation
__device__ int   g_bsel[M_];               // hard gumbel pick for negation
__device__ float g_AN[FV_*E_*M_];          // an[fv][e][m]
__device__ float g_AA[FV_*M_];
__device__ float g_BB[FV_*M_];
__device__ float g_invD[FV_*N_];           // 1/(sum_m |tn| + 1e-10)
__device__ int   g_negn[FV_*N_];           // any tn<0 along m for this (fv,n)
__device__ double g_powAB;
__device__ double g_cross;

__device__ __forceinline__ float clampf(float x, float lo, float hi){
    return fminf(fmaxf(x, lo), hi);
}

// ---------------- K0: init + hard gumbel selections ----------------
__global__ void k0_init(const float* __restrict__ coeff_act,
                        const float* __restrict__ coeff_neg,
                        const float* __restrict__ gum_act,
                        const float* __restrict__ gum_neg)
{
    int idx = blockIdx.x*256 + threadIdx.x;
    if (idx < N_) {
        g_gmin_bits[idx] = 0x7F800000u;   // +inf
        g_gs[idx] = 0.f;
        float v0 = clampf(coeff_act[idx],      -1.f, 1.f) + gum_act[idx];
        float v1 = clampf(coeff_act[N_+idx],   -1.f, 1.f) + gum_act[N_+idx];
        g_actsel[idx] = (v1 > v0) ? 1 : 0;    // argmax, ties -> 0 (first)
    }
    if (idx < M_) {
        float v0 = clampf(coeff_neg[idx],      -1.f, 1.f) + gum_neg[idx];
        float v1 = clampf(coeff_neg[M_+idx],   -1.f, 1.f) + gum_neg[M_+idx];
        g_bsel[idx] = (v1 > v0) ? 1 : 0;
    }
    if (idx == 0) { g_powAB = 0.0; g_cross = 0.0; }
}

// ---------------- K1: theta forward + column min of gi ----------------
// grid (4, 9), 1026 = 9*114 rows
__global__ void k1_theta(const float* __restrict__ theta_)
{
    int n  = blockIdx.x*256 + threadIdx.x;
    int m0 = blockIdx.y*114;
    float lmin = 3.4e38f;
    #pragma unroll 4
    for (int r=0; r<114; r++){
        int m = m0 + r;
        float t  = theta_[m*N_ + n];
        float tc = clampf(t, -1.f, 1.f);
        float gi = fabsf(tc);
        g_theta[m*N_ + n] = (gi < 0.01f) ? 0.f : tc;
        lmin = fminf(lmin, gi);
    }
    atomicMin(&g_gmin_bits[n], __float_as_uint(lmin));  // ok: gi >= 0
}

// ---------------- K2: gt = gi * (PGMIN/gmin[n]); gs[n] = sum_m gt ----------------
__global__ void k2_gt(const float* __restrict__ theta_)
{
    int n  = blockIdx.x*256 + threadIdx.x;
    int m0 = blockIdx.y*114;
    float ginv = 0.1f / __uint_as_float(g_gmin_bits[n]);
    float gssum = 0.f;
    #pragma unroll 4
    for (int r=0; r<114; r++){
        int m = m0 + r;
        float gi = fabsf(clampf(theta_[m*N_ + n], -1.f, 1.f));
        float g = gi * ginv;
        g_gt[m*N_ + n] = g;
        gssum += g;
    }
    atomicAdd(&g_gs[n], gssum);
}

// ---------------- K3: an buffer + AA/BB per (fv,m) ----------------
// grid (FV, 5)
__global__ void k3_an(const float* __restrict__ a)
{
    int fv = blockIdx.x;
    int m  = blockIdx.y*256 + threadIdx.x;
    if (m >= M_) return;
    int bs = g_bsel[m];
    float AA = 0.f, BB = 0.f;
    for (int e=0; e<E_; e++){
        float ax;
        if (m < NIN_)      ax = a[(fv*E_ + e)*NIN_ + m];
        else               ax = (m == NIN_) ? 1.f : 0.f;
        float an;
        if (m == M_-1)     an = 0.f;                       // an[..., -1] = 0
        else               an = bs ? (1.f/(1.f + expf(4.f*ax - 2.f)))  // sigmoid(4*(0.5-ax))
                                   : (1.f - ax);
        g_AN[(fv*E_ + e)*M_ + m] = an;
        AA += ax*ax;  BB += an*an;
    }
    g_AA[fv*M_ + m] = AA;
    g_BB[fv*M_ + m] = BB;
}

// ---------------- K4: D (-> invD), pos flags, AA/BB power term ----------------
// grid (FV, 4), 256 threads; thread owns (fv, n), loops all m
__global__ __launch_bounds__(256) void k4_D(const float* __restrict__ noise,
                                            const float* __restrict__ fault)
{
    int fv = blockIdx.x;
    int f  = fv >> 2;
    int n  = blockIdx.y*256 + threadIdx.x;
    float dsum = 0.f;
    float pab  = 0.f;
    int anyneg = 0;
    #pragma unroll 2
    for (int m=0; m<M_; m++){
        float th = g_theta[m*N_ + n];
        float u  = noise[(fv*M_ + m)*N_ + n];
        float fm = fault[(f*M_ + m)*N_ + n];
        float tn = th*(0.9f + 0.2f*u)*fm;
        dsum += fabsf(tn);
        float g = g_gt[m*N_ + n];
        if (tn >= 0.f) pab += g * g_AA[fv*M_ + m];
        else         { pab += g * g_BB[fv*M_ + m]; anyneg = 1; }
    }
    g_invD[fv*N_ + n] = 1.f/(dsum + 1e-10f);
    g_negn[fv*N_ + n] = anyneg;

    __shared__ double sred[256];
    sred[threadIdx.x] = (double)pab;
    __syncthreads();
    for (int s=128; s>0; s>>=1){
        if (threadIdx.x < s) sred[threadIdx.x] += sred[threadIdx.x+s];
        __syncthreads();
    }
    if (threadIdx.x == 0) atomicAdd(&g_powAB, sred[0]);
}

// ---------------- K5: fused dual GEMM (z, z2) + epilogue ----------------
// grid (FV, 16) — block computes z,z2 for (fv, e=0..63, n0..n0+63)
__global__ __launch_bounds__(256) void k5_main(const float* __restrict__ a,
                                               const float* __restrict__ noise,
                                               const float* __restrict__ fault,
                                               float* __restrict__ out)
{
    int fv = blockIdx.x;
    int f  = fv >> 2;
    int n0 = blockIdx.y * 64;
    int tid = threadIdx.x;

    __shared__ float ax_s[16][68];
    __shared__ float an_s[16][68];
    __shared__ float wp_s[16][64];
    __shared__ float wq_s[16][64];
    __shared__ float gp_s[16][64];
    __shared__ float gq_s[16][64];
    __shared__ int   s_neg;
    __shared__ double sred[256];

    if (tid == 0) s_neg = 0;
    __syncthreads();
    if (tid < 64) { if (g_negn[fv*N_ + n0 + tid]) s_neg = 1; }
    __syncthreads();
    const bool anyneg = (s_neg != 0);   // block-uniform

    const int nn = n0 + (tid & 63);     // staging column for B
    const int kb = tid >> 6;
    const float invD = g_invD[fv*N_ + nn];

    const int eg = tid >> 4;            // 0..15 -> rows e = eg*4+i
    const int ng = tid & 15;            // 0..15 -> cols n = n0+ng*4+j

    float z [4][4];
    float z2[4][4];
    #pragma unroll
    for (int i=0;i<4;i++)
        #pragma unroll
        for (int j=0;j<4;j++){ z[i][j]=0.f; z2[i][j]=0.f; }

    for (int t=0; t<65; t++){           // ceil(1026/16)
        int m0 = t*16;
        // -- stage A (ax / an), coalesced on m --
        {
            int k  = tid & 15;
            int e0 = tid >> 4;
            int m  = m0 + k;
            #pragma unroll
            for (int r=0; r<4; r++){
                int e = e0 + r*16;
                float axv;
                if (m < NIN_) axv = a[(fv*E_ + e)*NIN_ + m];
                else          axv = (m == NIN_) ? 1.f : 0.f;
                ax_s[k][e] = axv;
                if (anyneg)
                    an_s[k][e] = (m < M_) ? g_AN[(fv*E_ + e)*M_ + m] : 0.f;
            }
        }
        // -- stage B (on-the-fly weights), coalesced on n --
        #pragma unroll
        for (int kk=0; kk<4; kk++){
            int k = kk*4 + kb;
            int m = m0 + k;
            float wpv=0.f, wqv=0.f, gpv=0.f, gqv=0.f;
            if (m < M_){
                float th = g_theta[m*N_ + nn];
                float u  = noise[(fv*M_ + m)*N_ + nn];
                float fm = fault[(f*M_ + m)*N_ + nn];
                float tn = th*(0.9f + 0.2f*u)*fm;
                float g  = g_gt[m*N_ + nn];
                float w  = fabsf(tn)*invD;
                if (tn >= 0.f){ wpv = w; gpv = g; }
                else          { wqv = w; gqv = g; }
            }
            wp_s[k][tid&63] = wpv;  gp_s[k][tid&63] = gpv;
            if (anyneg){ wq_s[k][tid&63] = wqv;  gq_s[k][tid&63] = gqv; }
        }
        __syncthreads();

        if (!anyneg){
            #pragma unroll
            for (int k=0; k<16; k++){
                float4 axv = *(const float4*)&ax_s[k][eg*4];
                float4 wpv = *(const float4*)&wp_s[k][ng*4];
                float4 gpv = *(const float4*)&gp_s[k][ng*4];
                float axa[4]={axv.x,axv.y,axv.z,axv.w};
                float wpa[4]={wpv.x,wpv.y,wpv.z,wpv.w};
                float gpa[4]={gpv.x,gpv.y,gpv.z,gpv.w};
                #pragma unroll
                for (int i=0;i<4;i++)
                    #pragma unroll
                    for (int j=0;j<4;j++){
                        z [i][j] += axa[i]*wpa[j];
                        z2[i][j] += axa[i]*gpa[j];
                    }
            }
        } else {
            #pragma unroll
            for (int k=0; k<16; k++){
                float4 axv = *(const float4*)&ax_s[k][eg*4];
                float4 anv = *(const float4*)&an_s[k][eg*4];
                float4 wpv = *(const float4*)&wp_s[k][ng*4];
                float4 wqv = *(const float4*)&wq_s[k][ng*4];
                float4 gpv = *(const float4*)&gp_s[k][ng*4];
                float4 gqv = *(const float4*)&gq_s[k][ng*4];
                float axa[4]={axv.x,axv.y,axv.z,axv.w};
                float ana[4]={anv.x,anv.y,anv.z,anv.w};
                float wpa[4]={wpv.x,wpv.y,wpv.z,wpv.w};
                float wqa[4]={wqv.x,wqv.y,wqv.z,wqv.w};
                float gpa[4]={gpv.x,gpv.y,gpv.z,gpv.w};
                float gqa[4]={gqv.x,gqv.y,gqv.z,gqv.w};
                #pragma unroll
                for (int i=0;i<4;i++)
                    #pragma unroll
                    for (int j=0;j<4;j++){
                        z [i][j] += axa[i]*wpa[j] + ana[i]*wqa[j];
                        z2[i][j] += axa[i]*gpa[j] + ana[i]*gqa[j];
                    }
            }
        }
        __syncthreads();
    }

    // -- epilogue: activation -> out, power partials (double) --
    int nc0 = n0 + ng*4;
    float gsv[4]; int asv[4];
    #pragma unroll
    for (int j=0;j<4;j++){ gsv[j] = g_gs[nc0+j]; asv[j] = g_actsel[nc0+j]; }

    double cp = 0.0;
    #pragma unroll
    for (int i=0;i<4;i++){
        int e = eg*4 + i;
        float4 o;
        float* op = &o.x;
        #pragma unroll
        for (int j=0;j<4;j++){
            float zz = z[i][j];
            // ACT0 = sigmoid(4*(z-0.5)) ; ACT1 = tanh(z)
            float act = asv[j] ? tanhf(zz) : (1.f/(1.f + expf(2.f - 4.f*zz)));
            op[j] = act;
            cp += (double)zz * ((double)gsv[j]*(double)zz - 2.0*(double)z2[i][j]);
        }
        *(float4*)&out[(size_t)(fv*E_ + e)*N_ + nc0] = o;
    }
    sred[tid] = cp;
    __syncthreads();
    for (int s=128; s>0; s>>=1){
        if (tid < s) sred[tid] += sred[tid+s];
        __syncthreads();
    }
    if (tid == 0) atomicAdd(&g_cross, sred[0]);
}

// ---------------- K6: finalize power ----------------
__global__ void k6_fin(float* __restrict__ out)
{
    // power = (powAB - 2*sum(z*z2) + sum(gs*z^2)) / (E*V*F); cross already holds
    // (gs*z^2 - 2*z*z2) summed.
    out[(size_t)FV_*E_*N_] = (float)((g_powAB + g_cross) * (1.0/1024.0));
}

// ---------------- launch ----------------
extern "C" void kernel_launch(void* const* d_in, const int* in_sizes, int n_in,
                              void* d_out, int out_size)
{
    const float* a         = (const float*)d_in[0];
    const float* theta_    = (const float*)d_in[1];
    const float* coeff_act = (const float*)d_in[2];
    const float* coeff_neg = (const float*)d_in[3];
    const float* noise_u   = (const float*)d_in[4];
    const float* gum_act   = (const float*)d_in[5];
    const float* gum_neg   = (const float*)d_in[6];
    const float* fault     = (const float*)d_in[7];
    float* out = (float*)d_out;

    k0_init <<<5, 256>>>(coeff_act, coeff_neg, gum_act, gum_neg);
    k1_theta<<<dim3(4,9),  256>>>(theta_);
    k2_gt   <<<dim3(4,9),  256>>>(theta_);
    k3_an   <<<dim3(FV_,5),256>>>(a);
    k4_D    <<<dim3(FV_,4),256>>>(noise_u, fault);
    k5_main <<<dim3(FV_,16),256>>>(a, noise_u, fault, out);
    k6_fin  <<<1,1>>>(out);
}

// round 2
// speedup vs baseline: 2.8468x; 2.8468x over previous
#include <cuda_runtime.h>
#include <math.h>

#define F_ 4
#define V_ 4
#define E_ 64
#define NIN_ 1024
#define N_ 1024
#define M_ 1026
#define FV_ 16
#define NT_ 16    // n-tiles of 64

// ---------------- scratch ----------------
__device__ float g_theta[M_*N_];
__device__ float g_gt[M_*N_];
__device__ unsigned int g_gmin_bits[N_];
__device__ float g_gs[N_];
__device__ int   g_actsel[N_];
__device__ int   g_bsel[M_];
__device__ float g_AN[FV_*E_*M_];
__device__ float g_AAf[F_*M_];     // sum over v of AA[fv,m]
__device__ float g_BBf[F_*M_];
__device__ int   g_negflag[F_*NT_];
__device__ double g_powAB;
__device__ double g_cross;

__device__ __forceinline__ float clampf(float x, float lo, float hi){
    return fminf(fmaxf(x, lo), hi);
}

// ---------------- K0: init, zero, hard gumbel selections ----------------
__global__ void k0_init(const float* __restrict__ coeff_act,
                        const float* __restrict__ coeff_neg,
                        const float* __restrict__ gum_act,
                        const float* __restrict__ gum_neg)
{
    int idx = blockIdx.x*256 + threadIdx.x;
    if (idx < N_) {
        g_gmin_bits[idx] = 0x7F800000u;
        g_gs[idx] = 0.f;
        float v0 = clampf(coeff_act[idx],    -1.f, 1.f) + gum_act[idx];
        float v1 = clampf(coeff_act[N_+idx], -1.f, 1.f) + gum_act[N_+idx];
        g_actsel[idx] = (v1 > v0) ? 1 : 0;
    }
    if (idx < M_) {
        float v0 = clampf(coeff_neg[idx],    -1.f, 1.f) + gum_neg[idx];
        float v1 = clampf(coeff_neg[M_+idx], -1.f, 1.f) + gum_neg[M_+idx];
        g_bsel[idx] = (v1 > v0) ? 1 : 0;
    }
    if (idx < F_*M_) { g_AAf[idx] = 0.f; g_BBf[idx] = 0.f; }
    if (idx < F_*NT_) g_negflag[idx] = 0;
    if (idx == 0) { g_powAB = 0.0; g_cross = 0.0; }
}

// ---------------- K1: theta forward + column min of |clip(theta)| ----------------
__global__ void k1_theta(const float* __restrict__ theta_)
{
    int n  = blockIdx.x*256 + threadIdx.x;
    int m0 = blockIdx.y*114;
    float lmin = 3.4e38f;
    #pragma unroll 6
    for (int r=0; r<114; r++){
        int m = m0 + r;
        float tc = clampf(theta_[m*N_ + n], -1.f, 1.f);
        float gi = fabsf(tc);
        g_theta[m*N_ + n] = (gi < 0.01f) ? 0.f : tc;
        lmin = fminf(lmin, gi);
    }
    atomicMin(&g_gmin_bits[n], __float_as_uint(lmin));
}

// ---------------- K2: gt and gs ----------------
__global__ void k2_gt(const float* __restrict__ theta_)
{
    int n  = blockIdx.x*256 + threadIdx.x;
    int m0 = blockIdx.y*114;
    float ginv = 0.1f / __uint_as_float(g_gmin_bits[n]);
    float gssum = 0.f;
    #pragma unroll 6
    for (int r=0; r<114; r++){
        int m = m0 + r;
        float gi = fabsf(clampf(theta_[m*N_ + n], -1.f, 1.f));
        float g = gi * ginv;
        g_gt[m*N_ + n] = g;
        gssum += g;
    }
    atomicAdd(&g_gs[n], gssum);
}

// ---------------- K3: an buffer + per-f AA/BB sums (e-split x4) ----------------
__global__ void k3_an(const float* __restrict__ a)
{
    int fv = blockIdx.x;
    int m  = blockIdx.y*256 + threadIdx.x;
    int es = blockIdx.z;
    if (m >= M_) return;
    int bs = g_bsel[m];
    float AA = 0.f, BB = 0.f;
    #pragma unroll 4
    for (int r=0; r<16; r++){
        int e = es*16 + r;
        float ax;
        if (m < NIN_) ax = a[(fv*E_ + e)*NIN_ + m];
        else          ax = (m == NIN_) ? 1.f : 0.f;
        float an;
        if (m == M_-1) an = 0.f;
        else           an = bs ? (1.f/(1.f + expf(4.f*ax - 2.f))) : (1.f - ax);
        g_AN[(fv*E_ + e)*M_ + m] = an;
        AA += ax*ax;  BB += an*an;
    }
    int f = fv >> 2;
    atomicAdd(&g_AAf[f*M_ + m], AA);
    atomicAdd(&g_BBf[f*M_ + m], BB);
}

// ---------------- KSP: sign flags + powAB (noise-independent!) ----------------
// sign(tn) = sign(theta*fault) since (0.9+0.2u) > 0.
// powAB = sum_{f,v,m,n} gt*(p*AA + q*BB) = sum_{f,m,n} gt*(p*AAf + q*BBf)
__global__ __launch_bounds__(256) void ksp(const float* __restrict__ fault)
{
    int f  = blockIdx.x;
    int nt = blockIdx.y;
    int mc = blockIdx.z;
    int n  = nt*64 + (threadIdx.x & 63);
    int ms = threadIdx.x >> 6;
    int neg = 0;
    double pab = 0.0;
    #pragma unroll 4
    for (int r=0; r<32; r++){
        int m = mc*128 + r*4 + ms;
        if (m < M_){
            float th = g_theta[m*N_ + n];
            float fa = fault[(f*M_ + m)*N_ + n];
            float g  = g_gt[m*N_ + n];
            float s  = th*fa;
            if (s < 0.f){ neg = 1; pab += (double)(g * g_BBf[f*M_ + m]); }
            else        {          pab += (double)(g * g_AAf[f*M_ + m]); }
        }
    }
    if (neg) atomicOr(&g_negflag[f*NT_ + nt], 1);
    __shared__ double sred[256];
    sred[threadIdx.x] = pab;
    __syncthreads();
    for (int s=128; s>0; s>>=1){
        if (threadIdx.x < s) sred[threadIdx.x] += sred[threadIdx.x+s];
        __syncthreads();
    }
    if (threadIdx.x == 0) atomicAdd(&g_powAB, sred[0]);
}

// ---------------- K5: fully-fused dual GEMM + D + epilogue, software-pipelined --------
__global__ __launch_bounds__(256) void k5_main(const float* __restrict__ a,
                                               const float* __restrict__ noise,
                                               const float* __restrict__ fault,
                                               float* __restrict__ out)
{
    const int fv = blockIdx.x, f = fv >> 2;
    const int n0 = blockIdx.y * 64;
    const int tid = threadIdx.x;
    const bool anyneg = (g_negflag[f*NT_ + blockIdx.y] != 0);

    __shared__ float ax_s[16][68];
    __shared__ float an_s[16][68];
    __shared__ float wp_s[16][64];
    __shared__ float wq_s[16][64];
    __shared__ float gp_s[16][64];
    __shared__ float gq_s[16][64];
    __shared__ float dsum_s[4][64];
    __shared__ float invd_s[64];
    __shared__ double sred[256];

    const int ak = tid & 15, ae0 = tid >> 4;      // A-stage: col m=t*16+ak, rows ae0+16r
    const int nn = tid & 63, kb = tid >> 6;       // B-stage: column n0+nn, k = kk*4+kb
    const int eg = tid >> 4, ng = tid & 15;       // MMA: 4x4 at (eg*4, ng*4)

    const float* aB = a + (size_t)fv*E_*NIN_;

    float axr[4], anr[4], thr[4], nor[4], far[4], gtr[4];
    float dsum = 0.f;
    float z[4][4], z2[4][4];
    #pragma unroll
    for (int i=0;i<4;i++)
        #pragma unroll
        for (int j=0;j<4;j++){ z[i][j]=0.f; z2[i][j]=0.f; }

    // ---- prefetch t=0 ----
    {
        int m = ak;
        #pragma unroll
        for (int r=0;r<4;r++){
            int e = ae0 + r*16;
            axr[r] = (m < NIN_) ? aB[e*NIN_+m] : ((m==NIN_)?1.f:0.f);
            anr[r] = anyneg ? g_AN[(fv*E_+e)*M_+m] : 0.f;
        }
        #pragma unroll
        for (int kk=0;kk<4;kk++){
            int mm = kk*4 + kb;
            thr[kk] = g_theta[mm*N_ + n0+nn];
            nor[kk] = noise[((size_t)(fv*M_+mm))*N_ + n0+nn];
            far[kk] = fault[((size_t)(f*M_+mm))*N_ + n0+nn];
            gtr[kk] = g_gt[mm*N_ + n0+nn];
        }
    }

    for (int t=0; t<65; t++){
        __syncthreads();     // previous MMA done with smem
        // ---- stage regs -> smem (+ dsum) ----
        #pragma unroll
        for (int r=0;r<4;r++){
            ax_s[ak][ae0+r*16] = axr[r];
            if (anyneg) an_s[ak][ae0+r*16] = anr[r];
        }
        #pragma unroll
        for (int kk=0;kk<4;kk++){
            int k = kk*4 + kb;
            float tn = thr[kk]*(0.9f + 0.2f*nor[kk])*far[kk];
            float w  = fabsf(tn);
            dsum += w;
            if (!anyneg){
                wp_s[k][nn] = w;  gp_s[k][nn] = gtr[kk];
            } else {
                bool pos = (tn >= 0.f);
                wp_s[k][nn] = pos ? w : 0.f;
                wq_s[k][nn] = pos ? 0.f : w;
                gp_s[k][nn] = pos ? gtr[kk] : 0.f;
                gq_s[k][nn] = pos ? 0.f : gtr[kk];
            }
        }
        // ---- prefetch next tile (overlaps MMA) ----
        if (t < 64){
            int m = (t+1)*16 + ak;
            #pragma unroll
            for (int r=0;r<4;r++){
                int e = ae0 + r*16;
                axr[r] = (m < NIN_) ? aB[e*NIN_+m] : ((m==NIN_)?1.f:0.f);
                if (anyneg) anr[r] = (m < M_) ? g_AN[(fv*E_+e)*M_+m] : 0.f;
            }
            #pragma unroll
            for (int kk=0;kk<4;kk++){
                int mm = (t+1)*16 + kk*4 + kb;
                if (mm < M_){
                    thr[kk] = g_theta[mm*N_ + n0+nn];
                    nor[kk] = noise[((size_t)(fv*M_+mm))*N_ + n0+nn];
                    far[kk] = fault[((size_t)(f*M_+mm))*N_ + n0+nn];
                    gtr[kk] = g_gt[mm*N_ + n0+nn];
                } else { thr[kk]=0.f; nor[kk]=0.f; far[kk]=0.f; gtr[kk]=0.f; }
            }
        }
        __syncthreads();     // smem tile ready
        // ---- MMA ----
        if (!anyneg){
            #pragma unroll
            for (int k=0;k<16;k++){
                float4 axv = *(const float4*)&ax_s[k][eg*4];
                float4 wv  = *(const float4*)&wp_s[k][ng*4];
                float4 gv  = *(const float4*)&gp_s[k][ng*4];
                float axa[4]={axv.x,axv.y,axv.z,axv.w};
                float wa[4]={wv.x,wv.y,wv.z,wv.w};
                float ga[4]={gv.x,gv.y,gv.z,gv.w};
                #pragma unroll
                for (int i=0;i<4;i++)
                    #pragma unroll
                    for (int j=0;j<4;j++){
                        z [i][j] += axa[i]*wa[j];
                        z2[i][j] += axa[i]*ga[j];
                    }
            }
        } else {
            #pragma unroll
            for (int k=0;k<16;k++){
                float4 axv = *(const float4*)&ax_s[k][eg*4];
                float4 anv = *(const float4*)&an_s[k][eg*4];
                float4 wpv = *(const float4*)&wp_s[k][ng*4];
                float4 wqv = *(const float4*)&wq_s[k][ng*4];
                float4 gpv = *(const float4*)&gp_s[k][ng*4];
                float4 gqv = *(const float4*)&gq_s[k][ng*4];
                float axa[4]={axv.x,axv.y,axv.z,axv.w};
                float ana[4]={anv.x,anv.y,anv.z,anv.w};
                float wpa[4]={wpv.x,wpv.y,wpv.z,wpv.w};
                float wqa[4]={wqv.x,wqv.y,wqv.z,wqv.w};
                float gpa[4]={gpv.x,gpv.y,gpv.z,gpv.w};
                float gqa[4]={gqv.x,gqv.y,gqv.z,gqv.w};
                #pragma unroll
                for (int i=0;i<4;i++)
                    #pragma unroll
                    for (int j=0;j<4;j++){
                        z [i][j] += axa[i]*wpa[j] + ana[i]*wqa[j];
                        z2[i][j] += axa[i]*gpa[j] + ana[i]*gqa[j];
                    }
            }
        }
    }

    // ---- D reduction: 4 partials per column ----
    dsum_s[kb][nn] = dsum;
    __syncthreads();
    if (tid < 64)
        invd_s[tid] = 1.f/(dsum_s[0][tid]+dsum_s[1][tid]+dsum_s[2][tid]+dsum_s[3][tid] + 1e-10f);
    __syncthreads();

    // ---- epilogue ----
    int nc0 = n0 + ng*4;
    float gsv[4], inv[4]; int asv[4];
    #pragma unroll
    for (int j=0;j<4;j++){
        gsv[j] = g_gs[nc0+j];
        asv[j] = g_actsel[nc0+j];
        inv[j] = invd_s[ng*4+j];
    }
    double cp = 0.0;
    #pragma unroll
    for (int i=0;i<4;i++){
        int e = eg*4 + i;
        float4 o; float* op = &o.x;
        #pragma unroll
        for (int j=0;j<4;j++){
            float zz = z[i][j]*inv[j];
            float act = asv[j] ? tanhf(zz) : (1.f/(1.f + expf(2.f - 4.f*zz)));
            op[j] = act;
            cp += (double)zz * ((double)gsv[j]*(double)zz - 2.0*(double)z2[i][j]);
        }
        *(float4*)&out[(size_t)(fv*E_ + e)*N_ + nc0] = o;
    }
    sred[tid] = cp;
    __syncthreads();
    for (int s=128; s>0; s>>=1){
        if (tid < s) sred[tid] += sred[tid+s];
        __syncthreads();
    }
    if (tid == 0) atomicAdd(&g_cross, sred[0]);
}

// ---------------- K6: finalize power ----------------
__global__ void k6_fin(float* __restrict__ out)
{
    out[(size_t)FV_*E_*N_] = (float)((g_powAB + g_cross) * (1.0/1024.0));
}

// ---------------- launch ----------------
extern "C" void kernel_launch(void* const* d_in, const int* in_sizes, int n_in,
                              void* d_out, int out_size)
{
    const float* a         = (const float*)d_in[0];
    const float* theta_    = (const float*)d_in[1];
    const float* coeff_act = (const float*)d_in[2];
    const float* coeff_neg = (const float*)d_in[3];
    const float* noise_u   = (const float*)d_in[4];
    const float* gum_act   = (const float*)d_in[5];
    const float* gum_neg   = (const float*)d_in[6];
    const float* fault     = (const float*)d_in[7];
    float* out = (float*)d_out;

    k0_init <<<17, 256>>>(coeff_act, coeff_neg, gum_act, gum_neg);
    k1_theta<<<dim3(4,9),   256>>>(theta_);
    k2_gt   <<<dim3(4,9),   256>>>(theta_);
    k3_an   <<<dim3(FV_,5,4),256>>>(a);
    ksp     <<<dim3(F_,NT_,9),256>>>(fault);
    k5_main <<<dim3(FV_,NT_),256>>>(a, noise_u, fault, out);
    k6_fin  <<<1,1>>>(out);
}

// round 3
// speedup vs baseline: 4.5167x; 1.5866x over previous
#include <cuda_runtime.h>
#include <math.h>

#define F_ 4
#define V_ 4
#define E_ 64
#define NIN_ 1024
#define N_ 1024
#define M_ 1026
#define FV_ 16
#define NT_ 16

typedef unsigned long long u64;

__device__ __forceinline__ u64 pack2(float x){
    u64 r;
    asm("mov.b64 %0, {%1, %1};" : "=l"(r) : "r"(__float_as_uint(x)));
    return r;
}
__device__ __forceinline__ void ffma2(u64 &d, u64 a, u64 b){
    asm("fma.rn.f32x2 %0, %1, %2, %3;" : "=l"(d) : "l"(a), "l"(b), "l"(d));
}
__device__ __forceinline__ float lo2(u64 p){ return __uint_as_float((unsigned)p); }
__device__ __forceinline__ float hi2(u64 p){ return __uint_as_float((unsigned)(p>>32)); }

// ---------------- scratch ----------------
__device__ float g_theta[M_*N_];
__device__ float g_gt[M_*N_];
__device__ unsigned int g_gmin_bits[N_];
__device__ float g_gs[N_];
__device__ int   g_actsel[N_];
__device__ int   g_bsel[M_];
__device__ float g_AN[FV_*E_*M_];
__device__ float g_AAf[F_*M_];
__device__ float g_BBf[F_*M_];
__device__ int   g_negflag[F_*NT_];
__device__ double g_powAB;
__device__ double g_cross;

__device__ __forceinline__ float clampf(float x, float lo, float hi){
    return fminf(fmaxf(x, lo), hi);
}

// ---------------- K0 ----------------
__global__ void k0_init(const float* __restrict__ coeff_act,
                        const float* __restrict__ coeff_neg,
                        const float* __restrict__ gum_act,
                        const float* __restrict__ gum_neg)
{
    int idx = blockIdx.x*256 + threadIdx.x;
    if (idx < N_) {
        g_gmin_bits[idx] = 0x7F800000u;
        g_gs[idx] = 0.f;
        float v0 = clampf(coeff_act[idx],    -1.f, 1.f) + gum_act[idx];
        float v1 = clampf(coeff_act[N_+idx], -1.f, 1.f) + gum_act[N_+idx];
        g_actsel[idx] = (v1 > v0) ? 1 : 0;
    }
    if (idx < M_) {
        float v0 = clampf(coeff_neg[idx],    -1.f, 1.f) + gum_neg[idx];
        float v1 = clampf(coeff_neg[M_+idx], -1.f, 1.f) + gum_neg[M_+idx];
        g_bsel[idx] = (v1 > v0) ? 1 : 0;
    }
    if (idx < F_*M_) { g_AAf[idx] = 0.f; g_BBf[idx] = 0.f; }
    if (idx < F_*NT_) g_negflag[idx] = 0;
    if (idx == 0) { g_powAB = 0.0; g_cross = 0.0; }
}

// ---------------- K1 ----------------
__global__ void k1_theta(const float* __restrict__ theta_)
{
    int n  = blockIdx.x*256 + threadIdx.x;
    int m0 = blockIdx.y*114;
    float lmin = 3.4e38f;
    #pragma unroll 6
    for (int r=0; r<114; r++){
        int m = m0 + r;
        float tc = clampf(theta_[m*N_ + n], -1.f, 1.f);
        float gi = fabsf(tc);
        g_theta[m*N_ + n] = (gi < 0.01f) ? 0.f : tc;
        lmin = fminf(lmin, gi);
    }
    atomicMin(&g_gmin_bits[n], __float_as_uint(lmin));
}

// ---------------- K2 ----------------
__global__ void k2_gt(const float* __restrict__ theta_)
{
    int n  = blockIdx.x*256 + threadIdx.x;
    int m0 = blockIdx.y*114;
    float ginv = 0.1f / __uint_as_float(g_gmin_bits[n]);
    float gssum = 0.f;
    #pragma unroll 6
    for (int r=0; r<114; r++){
        int m = m0 + r;
        float gi = fabsf(clampf(theta_[m*N_ + n], -1.f, 1.f));
        float g = gi * ginv;
        g_gt[m*N_ + n] = g;
        gssum += g;
    }
    atomicAdd(&g_gs[n], gssum);
}

// ---------------- K3: an + per-f AA/BB (e-split x8) ----------------
__global__ void k3_an(const float* __restrict__ a)
{
    int fv = blockIdx.x;
    int m  = blockIdx.y*256 + threadIdx.x;
    int es = blockIdx.z;
    if (m >= M_) return;
    int bs = g_bsel[m];
    float AA = 0.f, BB = 0.f;
    #pragma unroll
    for (int r=0; r<8; r++){
        int e = es*8 + r;
        float ax;
        if (m < NIN_) ax = a[(fv*E_ + e)*NIN_ + m];
        else          ax = (m == NIN_) ? 1.f : 0.f;
        float an;
        if (m == M_-1) an = 0.f;
        else           an = bs ? (1.f/(1.f + expf(4.f*ax - 2.f))) : (1.f - ax);
        g_AN[(fv*E_ + e)*M_ + m] = an;
        AA += ax*ax;  BB += an*an;
    }
    int f = fv >> 2;
    atomicAdd(&g_AAf[f*M_ + m], AA);
    atomicAdd(&g_BBf[f*M_ + m], BB);
}

// ---------------- KSP: sign flags + powAB ----------------
__global__ __launch_bounds__(256) void ksp(const float* __restrict__ fault)
{
    int f  = blockIdx.x;
    int nt = blockIdx.y;
    int mc = blockIdx.z;
    int n  = nt*64 + (threadIdx.x & 63);
    int ms = threadIdx.x >> 6;
    int neg = 0;
    double pab = 0.0;
    #pragma unroll 4
    for (int r=0; r<32; r++){
        int m = mc*128 + r*4 + ms;
        if (m < M_){
            float th = g_theta[m*N_ + n];
            float fa = fault[(f*M_ + m)*N_ + n];
            float g  = g_gt[m*N_ + n];
            float s  = th*fa;
            if (s < 0.f){ neg = 1; pab += (double)(g * g_BBf[f*M_ + m]); }
            else        {          pab += (double)(g * g_AAf[f*M_ + m]); }
        }
    }
    if (neg) atomicOr(&g_negflag[f*NT_ + nt], 1);
    __shared__ double sred[256];
    sred[threadIdx.x] = pab;
    __syncthreads();
    for (int s=128; s>0; s>>=1){
        if (threadIdx.x < s) sred[threadIdx.x] += sred[threadIdx.x+s];
        __syncthreads();
    }
    if (threadIdx.x == 0) atomicAdd(&g_powAB, sred[0]);
}

// ---------------- K5: fused dual GEMM, packed f32x2 MMA ----------------
__global__ __launch_bounds__(256) void k5_main(const float* __restrict__ a,
                                               const float* __restrict__ noise,
                                               const float* __restrict__ fault,
                                               float* __restrict__ out)
{
    const int fv = blockIdx.x, f = fv >> 2;
    const int n0 = blockIdx.y * 64;
    const int tid = threadIdx.x;
    const bool anyneg = (g_negflag[f*NT_ + blockIdx.y] != 0);

    __shared__ float ax_s[16][68];
    __shared__ float an_s[16][68];
    __shared__ float wp_s[16][64];
    __shared__ float wq_s[16][64];
    __shared__ float gp_s[16][64];
    __shared__ float gq_s[16][64];
    __shared__ float dsum_s[4][64];
    __shared__ float invd_s[64];
    __shared__ double sred[256];

    const int ak = tid & 15, ae0 = tid >> 4;
    const int nn = tid & 63, kb = tid >> 6;
    const int eg = tid >> 4, ng = tid & 15;

    const float* aB = a + (size_t)fv*E_*NIN_;

    float axr[4], anr[4], thr[4], nor[4], far[4], gtr[4];
    float dsum = 0.f;
    u64 zp[4][2], z2p[4][2];
    #pragma unroll
    for (int i=0;i<4;i++){ zp[i][0]=0; zp[i][1]=0; z2p[i][0]=0; z2p[i][1]=0; }

    // ---- prefetch t=0 ----
    {
        int m = ak;
        #pragma unroll
        for (int r=0;r<4;r++){
            int e = ae0 + r*16;
            axr[r] = (m < NIN_) ? aB[e*NIN_+m] : ((m==NIN_)?1.f:0.f);
            anr[r] = anyneg ? g_AN[(fv*E_+e)*M_+m] : 0.f;
        }
        #pragma unroll
        for (int kk=0;kk<4;kk++){
            int mm = kk*4 + kb;
            thr[kk] = g_theta[mm*N_ + n0+nn];
            nor[kk] = noise[((size_t)(fv*M_+mm))*N_ + n0+nn];
            far[kk] = fault[((size_t)(f*M_+mm))*N_ + n0+nn];
            gtr[kk] = g_gt[mm*N_ + n0+nn];
        }
    }

    for (int t=0; t<65; t++){
        __syncthreads();
        // ---- stage regs -> smem (+ dsum) ----
        #pragma unroll
        for (int r=0;r<4;r++){
            ax_s[ak][ae0+r*16] = axr[r];
            if (anyneg) an_s[ak][ae0+r*16] = anr[r];
        }
        #pragma unroll
        for (int kk=0;kk<4;kk++){
            int k = kk*4 + kb;
            float tn = thr[kk]*(0.9f + 0.2f*nor[kk])*far[kk];
            float w  = fabsf(tn);
            dsum += w;
            if (!anyneg){
                wp_s[k][nn] = w;  gp_s[k][nn] = gtr[kk];
            } else {
                bool pos = (tn >= 0.f);
                wp_s[k][nn] = pos ? w : 0.f;
                wq_s[k][nn] = pos ? 0.f : w;
                gp_s[k][nn] = pos ? gtr[kk] : 0.f;
                gq_s[k][nn] = pos ? 0.f : gtr[kk];
            }
        }
        // ---- prefetch next tile ----
        if (t < 64){
            int m = (t+1)*16 + ak;
            #pragma unroll
            for (int r=0;r<4;r++){
                int e = ae0 + r*16;
                axr[r] = (m < NIN_) ? aB[e*NIN_+m] : ((m==NIN_)?1.f:0.f);
                if (anyneg) anr[r] = (m < M_) ? g_AN[(fv*E_+e)*M_+m] : 0.f;
            }
            #pragma unroll
            for (int kk=0;kk<4;kk++){
                int mm = (t+1)*16 + kk*4 + kb;
                if (mm < M_){
                    thr[kk] = g_theta[mm*N_ + n0+nn];
                    nor[kk] = noise[((size_t)(fv*M_+mm))*N_ + n0+nn];
                    far[kk] = fault[((size_t)(f*M_+mm))*N_ + n0+nn];
                    gtr[kk] = g_gt[mm*N_ + n0+nn];
                } else { thr[kk]=0.f; nor[kk]=0.f; far[kk]=0.f; gtr[kk]=0.f; }
            }
        }
        __syncthreads();
        // ---- MMA (packed f32x2) ----
        if (!anyneg){
            #pragma unroll
            for (int k=0;k<16;k++){
                float4 axv = *(const float4*)&ax_s[k][eg*4];
                u64 axp[4];
                axp[0]=pack2(axv.x); axp[1]=pack2(axv.y);
                axp[2]=pack2(axv.z); axp[3]=pack2(axv.w);
                const u64* wpp = (const u64*)&wp_s[k][ng*4];
                const u64* gpp = (const u64*)&gp_s[k][ng*4];
                u64 w0=wpp[0], w1=wpp[1], g0=gpp[0], g1=gpp[1];
                #pragma unroll
                for (int i=0;i<4;i++){
                    ffma2(zp[i][0],  axp[i], w0);
                    ffma2(zp[i][1],  axp[i], w1);
                    ffma2(z2p[i][0], axp[i], g0);
                    ffma2(z2p[i][1], axp[i], g1);
                }
            }
        } else {
            #pragma unroll
            for (int k=0;k<16;k++){
                float4 axv = *(const float4*)&ax_s[k][eg*4];
                float4 anv = *(const float4*)&an_s[k][eg*4];
                u64 axp[4], anp[4];
                axp[0]=pack2(axv.x); axp[1]=pack2(axv.y);
                axp[2]=pack2(axv.z); axp[3]=pack2(axv.w);
                anp[0]=pack2(anv.x); anp[1]=pack2(anv.y);
                anp[2]=pack2(anv.z); anp[3]=pack2(anv.w);
                const u64* wpp = (const u64*)&wp_s[k][ng*4];
                const u64* wqp = (const u64*)&wq_s[k][ng*4];
                const u64* gpp = (const u64*)&gp_s[k][ng*4];
                const u64* gqp = (const u64*)&gq_s[k][ng*4];
                u64 wp0=wpp[0], wp1=wpp[1], wq0=wqp[0], wq1=wqp[1];
                u64 gp0=gpp[0], gp1=gpp[1], gq0=gqp[0], gq1=gqp[1];
                #pragma unroll
                for (int i=0;i<4;i++){
                    ffma2(zp[i][0],  axp[i], wp0);
                    ffma2(zp[i][1],  axp[i], wp1);
                    ffma2(zp[i][0],  anp[i], wq0);
                    ffma2(zp[i][1],  anp[i], wq1);
                    ffma2(z2p[i][0], axp[i], gp0);
                    ffma2(z2p[i][1], axp[i], gp1);
                    ffma2(z2p[i][0], anp[i], gq0);
                    ffma2(z2p[i][1], anp[i], gq1);
                }
            }
        }
    }

    // ---- D reduction ----
    dsum_s[kb][nn] = dsum;
    __syncthreads();
    if (tid < 64)
        invd_s[tid] = 1.f/(dsum_s[0][tid]+dsum_s[1][tid]+dsum_s[2][tid]+dsum_s[3][tid] + 1e-10f);
    __syncthreads();

    // ---- epilogue ----
    int nc0 = n0 + ng*4;
    float gsv[4], inv[4]; int asv[4];
    #pragma unroll
    for (int j=0;j<4;j++){
        gsv[j] = g_gs[nc0+j];
        asv[j] = g_actsel[nc0+j];
        inv[j] = invd_s[ng*4+j];
    }
    double cp = 0.0;
    #pragma unroll
    for (int i=0;i<4;i++){
        int e = eg*4 + i;
        float zv[4]  = { lo2(zp[i][0]),  hi2(zp[i][0]),  lo2(zp[i][1]),  hi2(zp[i][1]) };
        float z2v[4] = { lo2(z2p[i][0]), hi2(z2p[i][0]), lo2(z2p[i][1]), hi2(z2p[i][1]) };
        float4 o; float* op = &o.x;
        #pragma unroll
        for (int j=0;j<4;j++){
            float zz = zv[j]*inv[j];
            float act = asv[j] ? tanhf(zz) : (1.f/(1.f + expf(2.f - 4.f*zz)));
            op[j] = act;
            cp += (double)zz * ((double)gsv[j]*(double)zz - 2.0*(double)z2v[j]);
        }
        *(float4*)&out[(size_t)(fv*E_ + e)*N_ + nc0] = o;
    }
    sred[tid] = cp;
    __syncthreads();
    for (int s=128; s>0; s>>=1){
        if (tid < s) sred[tid] += sred[tid+s];
        __syncthreads();
    }
    if (tid == 0) atomicAdd(&g_cross, sred[0]);
}

// ---------------- K6 ----------------
__global__ void k6_fin(float* __restrict__ out)
{
    out[(size_t)FV_*E_*N_] = (float)((g_powAB + g_cross) * (1.0/1024.0));
}

// ---------------- launch ----------------
extern "C" void kernel_launch(void* const* d_in, const int* in_sizes, int n_in,
                              void* d_out, int out_size)
{
    const float* a         = (const float*)d_in[0];
    const float* theta_    = (const float*)d_in[1];
    const float* coeff_act = (const float*)d_in[2];
    const float* coeff_neg = (const float*)d_in[3];
    const float* noise_u   = (const float*)d_in[4];
    const float* gum_act   = (const float*)d_in[5];
    const float* gum_neg   = (const float*)d_in[6];
    const float* fault     = (const float*)d_in[7];
    float* out = (float*)d_out;

    k0_init <<<17, 256>>>(coeff_act, coeff_neg, gum_act, gum_neg);
    k1_theta<<<dim3(4,9),    256>>>(theta_);
    k2_gt   <<<dim3(4,9),    256>>>(theta_);
    k3_an   <<<dim3(FV_,5,8),256>>>(a);
    ksp     <<<dim3(F_,NT_,9),256>>>(fault);
    k5_main <<<dim3(FV_,NT_),256>>>(a, noise_u, fault, out);
    k6_fin  <<<1,1>>>(out);
}